// round 1
// baseline (speedup 1.0000x reference)
#include <cuda_runtime.h>
#include <cstdint>

#define B_    4
#define N_    2048
#define FIN_  512
#define FOUT_ 128
#define ROWS_TOT (B_ * N_)

// Scratch (no cudaMalloc allowed)
__device__ float g_h[ROWS_TOT * FOUT_];   // 16 MB
__device__ float g_t1[ROWS_TOT];
__device__ float g_t2[ROWS_TOT];

// ---------------------------------------------------------------------------
// K1: h = X @ W   (8192 x 128, K=512), fp32.
// 64-row x 128-col block tile, 256 threads, 4x8 microtile, K-chunk 32.
// ---------------------------------------------------------------------------
__global__ __launch_bounds__(256) void k_gemm(const float* __restrict__ X,
                                              const float* __restrict__ W) {
    __shared__ float As[32][64];    // transposed: [k][row]
    __shared__ float Bs[32][128];   // [k][col]
    const int t = threadIdx.x;
    const int row0 = blockIdx.x * 64;
    const int ty = t >> 4;          // 0..15 -> rows 4*ty..
    const int tx = t & 15;          // 0..15 -> cols 8*tx..

    float acc[4][8];
#pragma unroll
    for (int r = 0; r < 4; r++)
#pragma unroll
        for (int c = 0; c < 8; c++) acc[r][c] = 0.f;

    for (int kc = 0; kc < FIN_; kc += 32) {
        // A tile: 64 rows x 32 k  = 512 float4, 2 per thread
#pragma unroll
        for (int l = 0; l < 2; l++) {
            int f = t + l * 256;
            int r = f >> 3;
            int kq = (f & 7) * 4;
            float4 v = *(const float4*)(X + (size_t)(row0 + r) * FIN_ + kc + kq);
            As[kq + 0][r] = v.x; As[kq + 1][r] = v.y;
            As[kq + 2][r] = v.z; As[kq + 3][r] = v.w;
        }
        // B tile: 32 k x 128 cols = 1024 float4, 4 per thread
#pragma unroll
        for (int l = 0; l < 4; l++) {
            int f = t + l * 256;
            int r = f >> 5;
            int c4 = (f & 31) * 4;
            *(float4*)(&Bs[r][c4]) = *(const float4*)(W + (size_t)(kc + r) * FOUT_ + c4);
        }
        __syncthreads();
#pragma unroll
        for (int kk = 0; kk < 32; kk++) {
            float4 a4 = *(const float4*)(&As[kk][ty * 4]);
            float4 b0 = *(const float4*)(&Bs[kk][tx * 8]);
            float4 b1 = *(const float4*)(&Bs[kk][tx * 8 + 4]);
            float av[4] = {a4.x, a4.y, a4.z, a4.w};
            float bv[8] = {b0.x, b0.y, b0.z, b0.w, b1.x, b1.y, b1.z, b1.w};
#pragma unroll
            for (int r = 0; r < 4; r++)
#pragma unroll
                for (int c = 0; c < 8; c++)
                    acc[r][c] = fmaf(av[r], bv[c], acc[r][c]);
        }
        __syncthreads();
    }
#pragma unroll
    for (int r = 0; r < 4; r++) {
        float* o = g_h + (size_t)(row0 + ty * 4 + r) * FOUT_ + tx * 8;
        *(float4*)(o)     = make_float4(acc[r][0], acc[r][1], acc[r][2], acc[r][3]);
        *(float4*)(o + 4) = make_float4(acc[r][4], acc[r][5], acc[r][6], acc[r][7]);
    }
}

// ---------------------------------------------------------------------------
// K2: t1 = h @ a1, t2 = h @ a2. One warp per row.
// ---------------------------------------------------------------------------
__global__ __launch_bounds__(256) void k_t12(const float* __restrict__ a1,
                                             const float* __restrict__ a2) {
    int gw = (blockIdx.x * 256 + threadIdx.x) >> 5;
    int lane = threadIdx.x & 31;
    if (gw >= ROWS_TOT) return;
    const float* hr = g_h + (size_t)gw * FOUT_;
    float s1 = 0.f, s2 = 0.f;
#pragma unroll
    for (int q = 0; q < 4; q++) {
        float hv = hr[lane + 32 * q];
        s1 = fmaf(hv, a1[lane + 32 * q], s1);
        s2 = fmaf(hv, a2[lane + 32 * q], s2);
    }
#pragma unroll
    for (int off = 16; off; off >>= 1) {
        s1 += __shfl_down_sync(0xffffffffu, s1, off);
        s2 += __shfl_down_sync(0xffffffffu, s2, off);
    }
    if (lane == 0) { g_t1[gw] = s1; g_t2[gw] = s2; }
}

// ---------------------------------------------------------------------------
// K3: fused masked-softmax attention aggregation (flash-style, fp32).
// Block = 32 query rows, loops over 16 chunks of 128 j's.
//   Phase 1: load h tile (128x128) + build P tile (32x128) + row partial sums
//   Phase 2: acc[i][o] += P[i][j] * h[j][o]
// No max-subtraction needed (|e| <= ~13, fp32-safe; masked w == 0 exactly).
// ---------------------------------------------------------------------------
__global__ __launch_bounds__(256) void k_attn(const int* __restrict__ adj,
                                              const int* __restrict__ d1p,
                                              const int* __restrict__ d2p,
                                              float* __restrict__ out) {
    extern __shared__ float sm[];
    float* h_sm = sm;                   // [128][128]
    float* P_sm = sm + 128 * 128;       // [32][132] (padded row stride)
    __shared__ float t1s[32];
    __shared__ float s_sm[32];

    const int t  = threadIdx.x;
    const int b  = blockIdx.x >> 6;         // 64 blocks per batch
    const int i0 = (blockIdx.x & 63) << 5;  // 32 rows per block
    const int d1 = *d1p, d2 = *d2p;
    const int w = t >> 5, lane = t & 31;
    const int il = t >> 4, jg = t & 15;     // P-phase mapping

    if (t < 32) { t1s[t] = g_t1[b * N_ + i0 + t]; s_sm[t] = 0.f; }
    __syncthreads();

    float acc[4][4];
#pragma unroll
    for (int a = 0; a < 4; a++)
        acc[a][0] = acc[a][1] = acc[a][2] = acc[a][3] = 0.f;

    const size_t adj_base = ((size_t)b * N_ + i0) * N_;

    for (int j0 = 0; j0 < N_; j0 += 128) {
        // --- load h tile: 4096 float4 / 256 threads ---
#pragma unroll
        for (int l = 0; l < 16; l++) {
            int f = t + l * 256;
            int jj = f >> 5;
            int o4 = (f & 31) * 4;
            *(float4*)(&h_sm[jj * 128 + o4]) =
                *(const float4*)(g_h + ((size_t)(b * N_) + j0 + jj) * FOUT_ + o4);
        }
        // --- t2 for my 8 j's (shared by both i iterations) ---
        float4 t2a = *(const float4*)(g_t2 + b * N_ + j0 + jg * 8);
        float4 t2b = *(const float4*)(g_t2 + b * N_ + j0 + jg * 8 + 4);
        float t2v[8] = {t2a.x, t2a.y, t2a.z, t2a.w, t2b.x, t2b.y, t2b.z, t2b.w};

        // --- P phase: each thread does 2 i's x 8 j's ---
#pragma unroll
        for (int s2 = 0; s2 < 32; s2 += 16) {
            int i = il + s2;
            float t1v = t1s[i];
            const int* arow = adj + adj_base + (size_t)i * N_ + j0 + jg * 8;
            int4 av0 = *(const int4*)(arow);
            int4 av1 = *(const int4*)(arow + 4);
            int avs[8] = {av0.x, av0.y, av0.z, av0.w, av1.x, av1.y, av1.z, av1.w};
            float p[8];
            float psum = 0.f;
#pragma unroll
            for (int k = 0; k < 8; k++) {
                float x = t1v + t2v[k];
                float e = fmaxf(x, 0.2f * x);                 // leaky relu
                float pv = (avs[k] == d1 || avs[k] == d2) ? __expf(e) : 0.f;
                p[k] = pv;
                psum += pv;
            }
            *(float4*)(&P_sm[i * 132 + jg * 8])     = make_float4(p[0], p[1], p[2], p[3]);
            *(float4*)(&P_sm[i * 132 + jg * 8 + 4]) = make_float4(p[4], p[5], p[6], p[7]);
#pragma unroll
            for (int off = 8; off; off >>= 1)
                psum += __shfl_down_sync(0xffffffffu, psum, off, 16);
            if (jg == 0) s_sm[i] += psum;   // unique writer per i
        }
        __syncthreads();

        // --- accumulate: warp w owns rows 4w..4w+3, lane owns o = lane*4..+3 ---
        const float* P0 = P_sm + (4 * w + 0) * 132;
        const float* P1 = P_sm + (4 * w + 1) * 132;
        const float* P2 = P_sm + (4 * w + 2) * 132;
        const float* P3 = P_sm + (4 * w + 3) * 132;
        const float* hp = h_sm + lane * 4;

#define GAT_STEP(U, C)                                                  \
        {                                                               \
            float4 hv = *(const float4*)(hb + (U) * 128);               \
            acc[0][0] = fmaf(q0.C, hv.x, acc[0][0]);                    \
            acc[0][1] = fmaf(q0.C, hv.y, acc[0][1]);                    \
            acc[0][2] = fmaf(q0.C, hv.z, acc[0][2]);                    \
            acc[0][3] = fmaf(q0.C, hv.w, acc[0][3]);                    \
            acc[1][0] = fmaf(q1.C, hv.x, acc[1][0]);                    \
            acc[1][1] = fmaf(q1.C, hv.y, acc[1][1]);                    \
            acc[1][2] = fmaf(q1.C, hv.z, acc[1][2]);                    \
            acc[1][3] = fmaf(q1.C, hv.w, acc[1][3]);                    \
            acc[2][0] = fmaf(q2.C, hv.x, acc[2][0]);                    \
            acc[2][1] = fmaf(q2.C, hv.y, acc[2][1]);                    \
            acc[2][2] = fmaf(q2.C, hv.z, acc[2][2]);                    \
            acc[2][3] = fmaf(q2.C, hv.w, acc[2][3]);                    \
            acc[3][0] = fmaf(q3.C, hv.x, acc[3][0]);                    \
            acc[3][1] = fmaf(q3.C, hv.y, acc[3][1]);                    \
            acc[3][2] = fmaf(q3.C, hv.z, acc[3][2]);                    \
            acc[3][3] = fmaf(q3.C, hv.w, acc[3][3]);                    \
        }

#pragma unroll 2
        for (int j4 = 0; j4 < 32; j4++) {
            float4 q0 = *(const float4*)(P0 + j4 * 4);
            float4 q1 = *(const float4*)(P1 + j4 * 4);
            float4 q2 = *(const float4*)(P2 + j4 * 4);
            float4 q3 = *(const float4*)(P3 + j4 * 4);
            const float* hb = hp + j4 * 4 * 128;
            GAT_STEP(0, x)
            GAT_STEP(1, y)
            GAT_STEP(2, z)
            GAT_STEP(3, w)
        }
#undef GAT_STEP
        __syncthreads();
    }

    // --- epilogue: normalize and store ---
#pragma unroll
    for (int ii = 0; ii < 4; ii++) {
        int i = 4 * w + ii;
        float inv = 1.0f / s_sm[i];
        float* o = out + ((size_t)(b * N_ + i0 + i)) * FOUT_ + lane * 4;
        *(float4*)o = make_float4(acc[ii][0] * inv, acc[ii][1] * inv,
                                  acc[ii][2] * inv, acc[ii][3] * inv);
    }
}

// ---------------------------------------------------------------------------
extern "C" void kernel_launch(void* const* d_in, const int* in_sizes, int n_in,
                              void* d_out, int out_size) {
    const float* X   = (const float*)d_in[0];
    const float* W   = (const float*)d_in[1];
    const float* a1  = (const float*)d_in[2];
    const float* a2  = (const float*)d_in[3];
    const int*   adj = (const int*)d_in[4];
    // d_in[5] = adj_tree: unused by the reference forward
    const int* d1p = (const int*)d_in[6];
    const int* d2p = (const int*)d_in[7];
    float* out = (float*)d_out;

    k_gemm<<<ROWS_TOT / 64, 256>>>(X, W);
    k_t12<<<(ROWS_TOT * 32) / 256, 256>>>(a1, a2);

    size_t smem = (size_t)(128 * 128 + 32 * 132) * sizeof(float);  // 82,432 B
    cudaFuncSetAttribute(k_attn, cudaFuncAttributeMaxDynamicSharedMemorySize,
                         (int)smem);
    k_attn<<<B_ * (N_ / 32), 256, smem>>>(adj, d1p, d2p, out);
}

// round 2
// speedup vs baseline: 1.1045x; 1.1045x over previous
#include <cuda_runtime.h>
#include <cstdint>

#define B_    4
#define N_    2048
#define FIN_  512
#define FOUT_ 128
#define ROWS_TOT (B_ * N_)

// Scratch (no cudaMalloc allowed)
__device__ float g_hp[2 * ROWS_TOT * FOUT_];  // split-K partials, 8 MB
__device__ float g_h[ROWS_TOT * FOUT_];       // 4 MB
__device__ float g_t1[ROWS_TOT];
__device__ float g_t2[ROWS_TOT];
__device__ float g_E1[ROWS_TOT];   // exp(t1)
__device__ float g_F1[ROWS_TOT];   // exp(0.2*t1)
__device__ float g_E2[ROWS_TOT];   // exp(t2)
__device__ float g_F2[ROWS_TOT];   // exp(0.2*t2)

// ---------------------------------------------------------------------------
// K1: h_partial = X @ W, split-K=2.
// grid (64, 2): 128-row x 128-col tile per CTA, K-range 256 per CTA.
// 256 threads, 8x8 microtile, K-chunk 32.
// ---------------------------------------------------------------------------
__global__ __launch_bounds__(256) void k_gemm(const float* __restrict__ X,
                                              const float* __restrict__ W) {
    __shared__ float As[32][132];   // [k][row], padded stride (528B, 16B-aligned)
    __shared__ float Bs[32][132];   // [k][col]
    const int t = threadIdx.x;
    const int row0 = blockIdx.x * 128;
    const int kb   = blockIdx.y * 256;
    const int tr = t >> 4;          // 0..15 -> rows 8*tr
    const int tc = t & 15;          // 0..15 -> cols 8*tc

    float acc[8][8];
#pragma unroll
    for (int r = 0; r < 8; r++)
#pragma unroll
        for (int c = 0; c < 8; c++) acc[r][c] = 0.f;

    for (int kc = 0; kc < 256; kc += 32) {
        // A tile: 128 rows x 32 k = 1024 float4, 4 per thread (store transposed)
#pragma unroll
        for (int l = 0; l < 4; l++) {
            int f = t + l * 256;
            int r = f >> 3;
            int kq = (f & 7) * 4;
            float4 v = *(const float4*)(X + (size_t)(row0 + r) * FIN_ + kb + kc + kq);
            As[kq + 0][r] = v.x; As[kq + 1][r] = v.y;
            As[kq + 2][r] = v.z; As[kq + 3][r] = v.w;
        }
        // B tile: 32 k x 128 cols = 1024 float4, 4 per thread
#pragma unroll
        for (int l = 0; l < 4; l++) {
            int f = t + l * 256;
            int kr = f >> 5;
            int c4 = (f & 31) * 4;
            *(float4*)(&Bs[kr][c4]) =
                *(const float4*)(W + (size_t)(kb + kc + kr) * FOUT_ + c4);
        }
        __syncthreads();
#pragma unroll
        for (int kk = 0; kk < 32; kk++) {
            float4 a0 = *(const float4*)(&As[kk][tr * 8]);
            float4 a1 = *(const float4*)(&As[kk][tr * 8 + 4]);
            float4 b0 = *(const float4*)(&Bs[kk][tc * 8]);
            float4 b1 = *(const float4*)(&Bs[kk][tc * 8 + 4]);
            float av[8] = {a0.x, a0.y, a0.z, a0.w, a1.x, a1.y, a1.z, a1.w};
            float bv[8] = {b0.x, b0.y, b0.z, b0.w, b1.x, b1.y, b1.z, b1.w};
#pragma unroll
            for (int r = 0; r < 8; r++)
#pragma unroll
                for (int c = 0; c < 8; c++)
                    acc[r][c] = fmaf(av[r], bv[c], acc[r][c]);
        }
        __syncthreads();
    }
    float* base = g_hp + (size_t)blockIdx.y * (ROWS_TOT * FOUT_);
#pragma unroll
    for (int r = 0; r < 8; r++) {
        float* o = base + (size_t)(row0 + tr * 8 + r) * FOUT_ + tc * 8;
        *(float4*)(o)     = make_float4(acc[r][0], acc[r][1], acc[r][2], acc[r][3]);
        *(float4*)(o + 4) = make_float4(acc[r][4], acc[r][5], acc[r][6], acc[r][7]);
    }
}

// ---------------------------------------------------------------------------
// K2: merge split-K partials -> g_h; t1 = h@a1, t2 = h@a2;
// precompute E/F = exp(t), exp(0.2 t) for the factorized leaky-relu-exp.
// One warp per row.
// ---------------------------------------------------------------------------
__global__ __launch_bounds__(256) void k_t12(const float* __restrict__ a1,
                                             const float* __restrict__ a2) {
    int gw = (blockIdx.x * 256 + threadIdx.x) >> 5;
    int lane = threadIdx.x & 31;
    if (gw >= ROWS_TOT) return;
    const float* p0 = g_hp + (size_t)gw * FOUT_;
    const float* p1 = g_hp + (size_t)ROWS_TOT * FOUT_ + (size_t)gw * FOUT_;
    float* hr = g_h + (size_t)gw * FOUT_;
    float s1 = 0.f, s2 = 0.f;
#pragma unroll
    for (int q = 0; q < 4; q++) {
        int c = lane + 32 * q;
        float hv = p0[c] + p1[c];
        hr[c] = hv;
        s1 = fmaf(hv, a1[c], s1);
        s2 = fmaf(hv, a2[c], s2);
    }
#pragma unroll
    for (int off = 16; off; off >>= 1) {
        s1 += __shfl_down_sync(0xffffffffu, s1, off);
        s2 += __shfl_down_sync(0xffffffffu, s2, off);
    }
    if (lane == 0) {
        g_t1[gw] = s1;
        g_t2[gw] = s2;
        g_E1[gw] = expf(s1);
        g_F1[gw] = expf(0.2f * s1);
        g_E2[gw] = expf(s2);
        g_F2[gw] = expf(0.2f * s2);
    }
}

// ---------------------------------------------------------------------------
// K3: fused masked-softmax attention aggregation, ZERO exp in the hot loop:
//   exp(lrelu(t1+t2)) = (t2 > -t1) ? E1*E2 : F1*F2
// Block = 32 query rows, 16 chunks of 128 j's. Unshifted softmax (fp32-safe).
// ---------------------------------------------------------------------------
__global__ __launch_bounds__(256) void k_attn(const int* __restrict__ adj,
                                              const int* __restrict__ d1p,
                                              const int* __restrict__ d2p,
                                              float* __restrict__ out) {
    extern __shared__ float sm[];
    float* h_sm = sm;                   // [128][128]
    float* P_sm = sm + 128 * 128;       // [32][132]
    __shared__ float nt1s[32], E1s[32], F1s[32], s_sm[32];

    const int t  = threadIdx.x;
    const int b  = blockIdx.x >> 6;
    const int i0 = (blockIdx.x & 63) << 5;
    const int d1 = *d1p, d2 = *d2p;
    const int w = t >> 5, lane = t & 31;
    const int il = t >> 4, jg = t & 15;

    if (t < 32) {
        int gi = b * N_ + i0 + t;
        nt1s[t] = -g_t1[gi];
        E1s[t]  = g_E1[gi];
        F1s[t]  = g_F1[gi];
        s_sm[t] = 0.f;
    }
    __syncthreads();

    float acc[4][4];
#pragma unroll
    for (int a = 0; a < 4; a++)
        acc[a][0] = acc[a][1] = acc[a][2] = acc[a][3] = 0.f;

    const size_t adj_base = ((size_t)b * N_ + i0) * N_;

    for (int j0 = 0; j0 < N_; j0 += 128) {
        // --- load h tile: 4096 float4 / 256 threads ---
#pragma unroll
        for (int l = 0; l < 16; l++) {
            int f = t + l * 256;
            int jj = f >> 5;
            int o4 = (f & 31) * 4;
            *(float4*)(&h_sm[jj * 128 + o4]) =
                *(const float4*)(g_h + ((size_t)(b * N_) + j0 + jj) * FOUT_ + o4);
        }
        // --- per-j data for my 8 j's ---
        int jb = b * N_ + j0 + jg * 8;
        float4 t2a = *(const float4*)(g_t2 + jb);
        float4 t2b = *(const float4*)(g_t2 + jb + 4);
        float4 e2a = *(const float4*)(g_E2 + jb);
        float4 e2b = *(const float4*)(g_E2 + jb + 4);
        float4 f2a = *(const float4*)(g_F2 + jb);
        float4 f2b = *(const float4*)(g_F2 + jb + 4);
        float t2v[8] = {t2a.x, t2a.y, t2a.z, t2a.w, t2b.x, t2b.y, t2b.z, t2b.w};
        float E2v[8] = {e2a.x, e2a.y, e2a.z, e2a.w, e2b.x, e2b.y, e2b.z, e2b.w};
        float F2v[8] = {f2a.x, f2a.y, f2a.z, f2a.w, f2b.x, f2b.y, f2b.z, f2b.w};

        // --- P phase: each thread does 2 i's x 8 j's, no MUFU ---
#pragma unroll
        for (int s2 = 0; s2 < 32; s2 += 16) {
            int i = il + s2;
            float nt1 = nt1s[i];
            float E1v = E1s[i], F1v = F1s[i];
            const int* arow = adj + adj_base + (size_t)i * N_ + j0 + jg * 8;
            int4 av0 = *(const int4*)(arow);
            int4 av1 = *(const int4*)(arow + 4);
            int avs[8] = {av0.x, av0.y, av0.z, av0.w, av1.x, av1.y, av1.z, av1.w};
            float p[8];
            float psum = 0.f;
#pragma unroll
            for (int k = 0; k < 8; k++) {
                bool pos = t2v[k] > nt1;               // t1 + t2 > 0
                float s1v = pos ? E1v : F1v;
                float s2v = pos ? E2v[k] : F2v[k];
                float pv = (avs[k] == d1 || avs[k] == d2) ? s1v * s2v : 0.f;
                p[k] = pv;
                psum += pv;
            }
            *(float4*)(&P_sm[i * 132 + jg * 8])     = make_float4(p[0], p[1], p[2], p[3]);
            *(float4*)(&P_sm[i * 132 + jg * 8 + 4]) = make_float4(p[4], p[5], p[6], p[7]);
#pragma unroll
            for (int off = 8; off; off >>= 1)
                psum += __shfl_down_sync(0xffffffffu, psum, off, 16);
            if (jg == 0) s_sm[i] += psum;
        }
        __syncthreads();

        // --- accumulate: warp w owns rows 4w..4w+3, lane owns cols lane*4..+3 ---
        const float* P0 = P_sm + (4 * w + 0) * 132;
        const float* P1 = P_sm + (4 * w + 1) * 132;
        const float* P2 = P_sm + (4 * w + 2) * 132;
        const float* P3 = P_sm + (4 * w + 3) * 132;
        const float* hp = h_sm + lane * 4;

#define GAT_STEP(U, C)                                                  \
        {                                                               \
            float4 hv = *(const float4*)(hb + (U) * 128);               \
            acc[0][0] = fmaf(q0.C, hv.x, acc[0][0]);                    \
            acc[0][1] = fmaf(q0.C, hv.y, acc[0][1]);                    \
            acc[0][2] = fmaf(q0.C, hv.z, acc[0][2]);                    \
            acc[0][3] = fmaf(q0.C, hv.w, acc[0][3]);                    \
            acc[1][0] = fmaf(q1.C, hv.x, acc[1][0]);                    \
            acc[1][1] = fmaf(q1.C, hv.y, acc[1][1]);                    \
            acc[1][2] = fmaf(q1.C, hv.z, acc[1][2]);                    \
            acc[1][3] = fmaf(q1.C, hv.w, acc[1][3]);                    \
            acc[2][0] = fmaf(q2.C, hv.x, acc[2][0]);                    \
            acc[2][1] = fmaf(q2.C, hv.y, acc[2][1]);                    \
            acc[2][2] = fmaf(q2.C, hv.z, acc[2][2]);                    \
            acc[2][3] = fmaf(q2.C, hv.w, acc[2][3]);                    \
            acc[3][0] = fmaf(q3.C, hv.x, acc[3][0]);                    \
            acc[3][1] = fmaf(q3.C, hv.y, acc[3][1]);                    \
            acc[3][2] = fmaf(q3.C, hv.z, acc[3][2]);                    \
            acc[3][3] = fmaf(q3.C, hv.w, acc[3][3]);                    \
        }

#pragma unroll 2
        for (int j4 = 0; j4 < 32; j4++) {
            float4 q0 = *(const float4*)(P0 + j4 * 4);
            float4 q1 = *(const float4*)(P1 + j4 * 4);
            float4 q2 = *(const float4*)(P2 + j4 * 4);
            float4 q3 = *(const float4*)(P3 + j4 * 4);
            const float* hb = hp + j4 * 4 * 128;
            GAT_STEP(0, x)
            GAT_STEP(1, y)
            GAT_STEP(2, z)
            GAT_STEP(3, w)
        }
#undef GAT_STEP
        __syncthreads();
    }

    // --- epilogue: normalize and store ---
#pragma unroll
    for (int ii = 0; ii < 4; ii++) {
        int i = 4 * w + ii;
        float inv = 1.0f / s_sm[i];
        float* o = out + ((size_t)(b * N_ + i0 + i)) * FOUT_ + lane * 4;
        *(float4*)o = make_float4(acc[ii][0] * inv, acc[ii][1] * inv,
                                  acc[ii][2] * inv, acc[ii][3] * inv);
    }
}

// ---------------------------------------------------------------------------
extern "C" void kernel_launch(void* const* d_in, const int* in_sizes, int n_in,
                              void* d_out, int out_size) {
    const float* X   = (const float*)d_in[0];
    const float* W   = (const float*)d_in[1];
    const float* a1  = (const float*)d_in[2];
    const float* a2  = (const float*)d_in[3];
    const int*   adj = (const int*)d_in[4];
    // d_in[5] = adj_tree: unused by the reference forward
    const int* d1p = (const int*)d_in[6];
    const int* d2p = (const int*)d_in[7];
    float* out = (float*)d_out;

    dim3 ggrid(ROWS_TOT / 128, 2);
    k_gemm<<<ggrid, 256>>>(X, W);
    k_t12<<<(ROWS_TOT * 32) / 256, 256>>>(a1, a2);

    size_t smem = (size_t)(128 * 128 + 32 * 132) * sizeof(float);  // 82,432 B
    cudaFuncSetAttribute(k_attn, cudaFuncAttributeMaxDynamicSharedMemorySize,
                         (int)smem);
    k_attn<<<B_ * (N_ / 32), 256, smem>>>(adj, d1p, d2p, out);
}

// round 4
// speedup vs baseline: 1.2045x; 1.0906x over previous
#include <cuda_runtime.h>
#include <cuda_bf16.h>
#include <cstdint>

#define B_    4
#define N_    2048
#define FIN_  512
#define FOUT_ 128
#define ROWS_TOT (B_ * N_)
#define PB    272   // byte pitch of bf16 smem tile rows (conflict-free for frag loads)

// ---------------- global scratch (no cudaMalloc allowed) --------------------
__device__ __align__(16) __nv_bfloat16 g_WTh[FOUT_ * FIN_];     // W^T hi [o][k]
__device__ __align__(16) __nv_bfloat16 g_WTl[FOUT_ * FIN_];     // W^T lo
__device__ __align__(16) __nv_bfloat16 g_hTh[B_ * FOUT_ * N_];  // h^T hi [b][o][j]
__device__ __align__(16) __nv_bfloat16 g_hTl[B_ * FOUT_ * N_];  // h^T lo
__device__ float g_t1[ROWS_TOT], g_t2[ROWS_TOT];
__device__ float g_E1[ROWS_TOT], g_F1[ROWS_TOT];
__device__ float g_E2[ROWS_TOT], g_F2[ROWS_TOT];

// ---------------- helpers ----------------------------------------------------
__device__ __forceinline__ void mma_bf16(float* c,
    uint32_t a0, uint32_t a1, uint32_t a2, uint32_t a3,
    uint32_t b0, uint32_t b1) {
    asm volatile(
        "mma.sync.aligned.m16n8k16.row.col.f32.bf16.bf16.f32 "
        "{%0,%1,%2,%3},{%4,%5,%6,%7},{%8,%9},{%0,%1,%2,%3};"
        : "+f"(c[0]), "+f"(c[1]), "+f"(c[2]), "+f"(c[3])
        : "r"(a0), "r"(a1), "r"(a2), "r"(a3), "r"(b0), "r"(b1));
}
__device__ __forceinline__ uint32_t bf2u(__nv_bfloat162 v) {
    return *reinterpret_cast<uint32_t*>(&v);
}
__device__ __forceinline__ void split2(float a, float b, uint32_t& hi, uint32_t& lo) {
    __nv_bfloat162 h = __floats2bfloat162_rn(a, b);
    __nv_bfloat162 l = __floats2bfloat162_rn(a - __bfloat162float(h.x),
                                             b - __bfloat162float(h.y));
    hi = bf2u(h); lo = bf2u(l);
}

// ---------------------------------------------------------------------------
// K0: W[512,128] -> W^T hi/lo bf16 [128][512]
// ---------------------------------------------------------------------------
__global__ void k_wprep(const float* __restrict__ W) {
    __shared__ float tile[32][33];
    int k0 = blockIdx.x * 32, n0 = blockIdx.y * 32;
    int tx = threadIdx.x, ty = threadIdx.y;
#pragma unroll
    for (int r = 0; r < 4; r++)
        tile[ty + 8 * r][tx] = W[(size_t)(k0 + ty + 8 * r) * FOUT_ + n0 + tx];
    __syncthreads();
#pragma unroll
    for (int r = 0; r < 4; r++) {
        int n = n0 + ty + 8 * r, k = k0 + tx;
        float x = tile[tx][ty + 8 * r];
        __nv_bfloat16 h = __float2bfloat16_rn(x);
        __nv_bfloat16 l = __float2bfloat16_rn(x - __bfloat162float(h));
        g_WTh[(size_t)n * FIN_ + k] = h;
        g_WTl[(size_t)n * FIN_ + k] = l;
    }
}

// ---------------------------------------------------------------------------
// K1: h = X @ W via mma.sync bf16 hi/lo split (3 MMAs). CTA = 64 rows x 128 o.
// Epilogue: t1/t2 + exp tables + h^T hi/lo bf16 to global.
// ---------------------------------------------------------------------------
#define GXH 0
#define GXL 17408
#define GWH 34816
#define GWL 69632
#define GA1 104448
#define GA2 104960
#define GSM 105472

__global__ __launch_bounds__(256) void k_gemm_tc(const float* __restrict__ X,
                                                 const float* __restrict__ a1,
                                                 const float* __restrict__ a2) {
    extern __shared__ char sm[];
    const int t = threadIdx.x, w = t >> 5, lane = t & 31;
    const int g = lane >> 2, tig = lane & 3;
    const int wm = w & 3, wn = w >> 2;
    const int row0 = blockIdx.x * 64;

    if (t < 128) {
        ((float*)(sm + GA1))[t] = a1[t];
        ((float*)(sm + GA2))[t] = a2[t];
    }

    float acc[8][4];
#pragma unroll
    for (int nt = 0; nt < 8; nt++)
        acc[nt][0] = acc[nt][1] = acc[nt][2] = acc[nt][3] = 0.f;

    for (int c = 0; c < 8; c++) {
        const int kc = c * 64;
        // X tile 64x64 f32 -> bf16 hi/lo
#pragma unroll
        for (int l = 0; l < 4; l++) {
            int f = t + l * 256;
            int m = f >> 4, kq = (f & 15) * 4;
            float4 v = *(const float4*)(X + (size_t)(row0 + m) * FIN_ + kc + kq);
            uint32_t h0, l0, h1, l1;
            split2(v.x, v.y, h0, l0);
            split2(v.z, v.w, h1, l1);
            *(uint2*)(sm + GXH + m * PB + kq * 2) = make_uint2(h0, h1);
            *(uint2*)(sm + GXL + m * PB + kq * 2) = make_uint2(l0, l1);
        }
        // W^T tile 128x64 (pre-split bf16)
#pragma unroll
        for (int l = 0; l < 4; l++) {
            int f = t + l * 256;
            int n = f >> 3, kq = (f & 7) * 8;
            *(uint4*)(sm + GWH + n * PB + kq * 2) =
                *(const uint4*)(g_WTh + (size_t)n * FIN_ + kc + kq);
            *(uint4*)(sm + GWL + n * PB + kq * 2) =
                *(const uint4*)(g_WTl + (size_t)n * FIN_ + kc + kq);
        }
        __syncthreads();
#pragma unroll
        for (int ks = 0; ks < 4; ks++) {
            const int kb = (ks * 16 + 2 * tig) * 2;
            const int ra = (wm * 16 + g) * PB, rb = (wm * 16 + g + 8) * PB;
            uint32_t ah0 = *(const uint32_t*)(sm + GXH + ra + kb);
            uint32_t ah1 = *(const uint32_t*)(sm + GXH + rb + kb);
            uint32_t ah2 = *(const uint32_t*)(sm + GXH + ra + kb + 16);
            uint32_t ah3 = *(const uint32_t*)(sm + GXH + rb + kb + 16);
            uint32_t al0 = *(const uint32_t*)(sm + GXL + ra + kb);
            uint32_t al1 = *(const uint32_t*)(sm + GXL + rb + kb);
            uint32_t al2 = *(const uint32_t*)(sm + GXL + ra + kb + 16);
            uint32_t al3 = *(const uint32_t*)(sm + GXL + rb + kb + 16);
#pragma unroll
            for (int nt = 0; nt < 8; nt++) {
                const int n = (wn * 64 + nt * 8 + g) * PB;
                uint32_t bh0 = *(const uint32_t*)(sm + GWH + n + kb);
                uint32_t bh1 = *(const uint32_t*)(sm + GWH + n + kb + 16);
                uint32_t bl0 = *(const uint32_t*)(sm + GWL + n + kb);
                uint32_t bl1 = *(const uint32_t*)(sm + GWL + n + kb + 16);
                mma_bf16(acc[nt], ah0, ah1, ah2, ah3, bh0, bh1);
                mma_bf16(acc[nt], ah0, ah1, ah2, ah3, bl0, bl1);
                mma_bf16(acc[nt], al0, al1, al2, al3, bh0, bh1);
            }
        }
        __syncthreads();
    }

    // ---- epilogue: stage D in smem (overlays X tiles), then t1/t2/hT ----
    float* Ds = (float*)sm;   // [64][132] f32 = 33792 B (< GWH, A1/A2 untouched)
    {
        const int r = wm * 16 + g, cl = wn * 64 + 2 * tig;
#pragma unroll
        for (int nt = 0; nt < 8; nt++) {
            Ds[r * 132 + cl + nt * 8]           = acc[nt][0];
            Ds[r * 132 + cl + nt * 8 + 1]       = acc[nt][1];
            Ds[(r + 8) * 132 + cl + nt * 8]     = acc[nt][2];
            Ds[(r + 8) * 132 + cl + nt * 8 + 1] = acc[nt][3];
        }
    }
    __syncthreads();
    const float* A1 = (const float*)(sm + GA1);
    const float* A2 = (const float*)(sm + GA2);
    // t1/t2: warp w handles rows 8w..8w+7
#pragma unroll
    for (int rr = 0; rr < 8; rr++) {
        int r = w * 8 + rr;
        float s1 = 0.f, s2 = 0.f;
#pragma unroll
        for (int q = 0; q < 4; q++) {
            float v = Ds[r * 132 + lane + 32 * q];
            s1 = fmaf(v, A1[lane + 32 * q], s1);
            s2 = fmaf(v, A2[lane + 32 * q], s2);
        }
#pragma unroll
        for (int o = 16; o; o >>= 1) {
            s1 += __shfl_down_sync(0xffffffffu, s1, o);
            s2 += __shfl_down_sync(0xffffffffu, s2, o);
        }
        if (lane == 0) {
            int gr = row0 + r;
            g_t1[gr] = s1;  g_t2[gr] = s2;
            g_E1[gr] = expf(s1);          g_E2[gr] = expf(s2);
            g_F1[gr] = expf(0.2f * s1);   g_F2[gr] = expf(0.2f * s2);
        }
    }
    // hT hi/lo: thread -> (o = t&127, half = t>>7), 32 consecutive i each
    {
        const int o = t & 127, half = t >> 7;
        const int bb = row0 >> 11, j0 = row0 & (N_ - 1);
        uint32_t uh[16], ul[16];
#pragma unroll
        for (int ii = 0; ii < 16; ii++) {
            float v0 = Ds[(half * 32 + 2 * ii) * 132 + o];
            float v1 = Ds[(half * 32 + 2 * ii + 1) * 132 + o];
            split2(v0, v1, uh[ii], ul[ii]);
        }
        size_t base = ((size_t)(bb * FOUT_ + o)) * N_ + j0 + half * 32;
#pragma unroll
        for (int q = 0; q < 4; q++) {
            *(uint4*)(g_hTh + base + q * 8) =
                make_uint4(uh[4 * q], uh[4 * q + 1], uh[4 * q + 2], uh[4 * q + 3]);
            *(uint4*)(g_hTl + base + q * 8) =
                make_uint4(ul[4 * q], ul[4 * q + 1], ul[4 * q + 2], ul[4 * q + 3]);
        }
    }
}

// ---------------------------------------------------------------------------
// K2: fused masked-softmax attention via mma.sync bf16 split.
// CTA = 64 i-rows; 16 chunks of 128 j. P built directly in A-fragments.
// ---------------------------------------------------------------------------
#define ABH0 0
#define ABL0 34816
#define ABH1 69632
#define ABL1 104448
#define AT2  139264
#define AE2  147456
#define AF2  155648
#define ASM  163840

__device__ __forceinline__ float pcalc(int a, float t2v, float e2, float f2,
                                       float nt1, float E1, float F1,
                                       int d1, int d2) {
    bool pos = t2v > nt1;                 // t1 + t2 > 0
    float m1 = pos ? E1 : F1;
    float m2 = pos ? e2 : f2;
    return (a == d1 || a == d2) ? m1 * m2 : 0.f;
}

__global__ __launch_bounds__(256) void k_attn_tc(const int* __restrict__ adj,
                                                 const int* __restrict__ d1p,
                                                 const int* __restrict__ d2p,
                                                 float* __restrict__ out) {
    extern __shared__ char sm[];
    const int t = threadIdx.x, w = t >> 5, lane = t & 31;
    const int g = lane >> 2, tig = lane & 3;
    const int wm = w & 3, wn = w >> 2;
    const int b = blockIdx.x >> 5, i0 = (blockIdx.x & 31) * 64;
    const int d1 = *d1p, d2 = *d2p;

    float* T2 = (float*)(sm + AT2);
    float* E2 = (float*)(sm + AE2);
    float* F2 = (float*)(sm + AF2);
#pragma unroll
    for (int l = 0; l < 2; l++) {
        int f = t + l * 256;
        ((float4*)T2)[f] = ((const float4*)(g_t2 + b * N_))[f];
        ((float4*)E2)[f] = ((const float4*)(g_E2 + b * N_))[f];
        ((float4*)F2)[f] = ((const float4*)(g_F2 + b * N_))[f];
    }

    const int r0 = i0 + wm * 16 + g, r1 = r0 + 8;
    const int gr0 = b * N_ + r0, gr1 = b * N_ + r1;
    const float nt10 = -g_t1[gr0], E10 = g_E1[gr0], F10 = g_F1[gr0];
    const float nt11 = -g_t1[gr1], E11 = g_E1[gr1], F11 = g_F1[gr1];
    const size_t ab0 = (size_t)gr0 * N_, ab1 = (size_t)gr1 * N_;
    const size_t hbase = (size_t)b * FOUT_ * N_;

    float acc[8][4];
#pragma unroll
    for (int nt = 0; nt < 8; nt++)
        acc[nt][0] = acc[nt][1] = acc[nt][2] = acc[nt][3] = 0.f;
    float s0 = 0.f, s1s = 0.f;

    const int lo_ = t >> 1, seg = t & 1;           // B-tile loader mapping
    const size_t lsrc = hbase + (size_t)lo_ * N_ + seg * 64;
    char* const ldsth0 = sm + (size_t)lo_ * PB + seg * 128;

    // preload chunk 0 into buf 0
    {
#pragma unroll
        for (int q = 0; q < 8; q++) {
            *(uint4*)(ldsth0 + ABH0 + q * 16) = *(const uint4*)(g_hTh + lsrc + q * 8);
            *(uint4*)(ldsth0 + ABL0 + q * 16) = *(const uint4*)(g_hTl + lsrc + q * 8);
        }
    }

    for (int c = 0; c < 16; c++) {
        const int buf = c & 1;
        __syncthreads();
        if (c < 15) {   // prefetch next chunk into the other buffer
            const size_t src = lsrc + (size_t)(c + 1) * 128;
            char* dh = ldsth0 + (buf ? ABH0 : ABH1);
            char* dl = ldsth0 + (buf ? ABL0 : ABL1);
#pragma unroll
            for (int q = 0; q < 8; q++) {
                *(uint4*)(dh + q * 16) = *(const uint4*)(g_hTh + src + q * 8);
                *(uint4*)(dl + q * 16) = *(const uint4*)(g_hTl + src + q * 8);
            }
        }
        const char* BHc = sm + (buf ? ABH1 : ABH0);
        const char* BLc = sm + (buf ? ABL1 : ABL0);
        const int j0 = c * 128;
#pragma unroll
        for (int ks = 0; ks < 8; ks++) {
            const int c0 = j0 + ks * 16 + 2 * tig;
            int2 q00 = *(const int2*)(adj + ab0 + c0);
            int2 q01 = *(const int2*)(adj + ab0 + c0 + 8);
            int2 q10 = *(const int2*)(adj + ab1 + c0);
            int2 q11 = *(const int2*)(adj + ab1 + c0 + 8);
            float2 t2a = *(const float2*)(T2 + c0), t2b = *(const float2*)(T2 + c0 + 8);
            float2 e2a = *(const float2*)(E2 + c0), e2b = *(const float2*)(E2 + c0 + 8);
            float2 f2a = *(const float2*)(F2 + c0), f2b = *(const float2*)(F2 + c0 + 8);

            float p00 = pcalc(q00.x, t2a.x, e2a.x, f2a.x, nt10, E10, F10, d1, d2);
            float p01 = pcalc(q00.y, t2a.y, e2a.y, f2a.y, nt10, E10, F10, d1, d2);
            float p02 = pcalc(q01.x, t2b.x, e2b.x, f2b.x, nt10, E10, F10, d1, d2);
            float p03 = pcalc(q01.y, t2b.y, e2b.y, f2b.y, nt10, E10, F10, d1, d2);
            float p10 = pcalc(q10.x, t2a.x, e2a.x, f2a.x, nt11, E11, F11, d1, d2);
            float p11 = pcalc(q10.y, t2a.y, e2a.y, f2a.y, nt11, E11, F11, d1, d2);
            float p12 = pcalc(q11.x, t2b.x, e2b.x, f2b.x, nt11, E11, F11, d1, d2);
            float p13 = pcalc(q11.y, t2b.y, e2b.y, f2b.y, nt11, E11, F11, d1, d2);
            s0  += (p00 + p01) + (p02 + p03);
            s1s += (p10 + p11) + (p12 + p13);

            uint32_t ah0, al0, ah1, al1, ah2, al2, ah3, al3;
            split2(p00, p01, ah0, al0);    // row r0,  k
            split2(p10, p11, ah1, al1);    // row r1,  k
            split2(p02, p03, ah2, al2);    // row r0,  k+8
            split2(p12, p13, ah3, al3);    // row r1,  k+8

            const int kb = (ks * 16 + 2 * tig) * 2;
#pragma unroll
            for (int nt = 0; nt < 8; nt++) {
                const int n = (wn * 64 + nt * 8 + g) * PB;
                uint32_t bh0 = *(const uint32_t*)(BHc + n + kb);
                uint32_t bh1 = *(const uint32_t*)(BHc + n + kb + 16);
                uint32_t bl0 = *(const uint32_t*)(BLc + n + kb);
                uint32_t bl1 = *(const uint32_t*)(BLc + n + kb + 16);
                mma_bf16(acc[nt], ah0, ah1, ah2, ah3, bh0, bh1);
                mma_bf16(acc[nt], ah0, ah1, ah2, ah3, bl0, bl1);
                mma_bf16(acc[nt], al0, al1, al2, al3, bh0, bh1);
            }
        }
    }

    // row sums: reduce over the 4-lane quad (tig), then broadcast
    float v0 = s0, v1 = s1s;
    v0 += __shfl_down_sync(0xffffffffu, v0, 2, 4);
    v0 += __shfl_down_sync(0xffffffffu, v0, 1, 4);
    v1 += __shfl_down_sync(0xffffffffu, v1, 2, 4);
    v1 += __shfl_down_sync(0xffffffffu, v1, 1, 4);
    v0 = __shfl_sync(0xffffffffu, v0, lane & ~3);
    v1 = __shfl_sync(0xffffffffu, v1, lane & ~3);
    const float inv0 = 1.0f / v0, inv1 = 1.0f / v1;

#pragma unroll
    for (int nt = 0; nt < 8; nt++) {
        const int cl = wn * 64 + nt * 8 + 2 * tig;
        *(float2*)(out + (size_t)gr0 * FOUT_ + cl) =
            make_float2(acc[nt][0] * inv0, acc[nt][1] * inv0);
        *(float2*)(out + (size_t)gr1 * FOUT_ + cl) =
            make_float2(acc[nt][2] * inv1, acc[nt][3] * inv1);
    }
}

// ---------------------------------------------------------------------------
extern "C" void kernel_launch(void* const* d_in, const int* in_sizes, int n_in,
                              void* d_out, int out_size) {
    const float* X   = (const float*)d_in[0];
    const float* W   = (const float*)d_in[1];
    const float* a1  = (const float*)d_in[2];
    const float* a2  = (const float*)d_in[3];
    const int*   adj = (const int*)d_in[4];
    // d_in[5] = adj_tree: unused by the reference forward
    const int* d1p = (const int*)d_in[6];
    const int* d2p = (const int*)d_in[7];
    float* out = (float*)d_out;

    k_wprep<<<dim3(FIN_ / 32, FOUT_ / 32), dim3(32, 8)>>>(W);

    cudaFuncSetAttribute(k_gemm_tc, cudaFuncAttributeMaxDynamicSharedMemorySize, GSM);
    k_gemm_tc<<<ROWS_TOT / 64, 256, GSM>>>(X, a1, a2);

    cudaFuncSetAttribute(k_attn_tc, cudaFuncAttributeMaxDynamicSharedMemorySize, ASM);
    k_attn_tc<<<B_ * (N_ / 64), 256, ASM>>>(adj, d1p, d2p, out);
}

// round 5
// speedup vs baseline: 1.6308x; 1.3538x over previous
#include <cuda_runtime.h>
#include <cuda_bf16.h>
#include <cuda_fp16.h>
#include <cstdint>

#define B_    4
#define N_    2048
#define FIN_  512
#define FOUT_ 128
#define ROWS_TOT (B_ * N_)
#define PB    272    // bf16 gemm tile pitch (bytes)
#define TROWS 144    // padded o-rows in hE/hF (128 data + 1 sums + 15 zero)
#define PB2   144    // attn B-tile pitch (bytes): 64 fp16 = 128B + 16 pad
#define TILE_B (TROWS * PB2)   // 20736

// ---------------- global scratch (no cudaMalloc allowed) --------------------
__device__ __align__(16) __nv_bfloat16 g_WTh[FOUT_ * FIN_];
__device__ __align__(16) __nv_bfloat16 g_WTl[FOUT_ * FIN_];
__device__ __align__(16) __half g_hE[B_ * TROWS * N_];   // [b][o][j]: E2[j]*h, row128=E2, 129+ =0
__device__ __align__(16) __half g_hF[B_ * TROWS * N_];   // F2 variant
__device__ float g_t1[ROWS_TOT], g_t2[ROWS_TOT];
__device__ float g_E1[ROWS_TOT], g_F1[ROWS_TOT];

// ---------------- helpers ----------------------------------------------------
__device__ __forceinline__ void mma_bf16(float* c,
    uint32_t a0, uint32_t a1, uint32_t a2, uint32_t a3, uint32_t b0, uint32_t b1) {
    asm volatile(
        "mma.sync.aligned.m16n8k16.row.col.f32.bf16.bf16.f32 "
        "{%0,%1,%2,%3},{%4,%5,%6,%7},{%8,%9},{%0,%1,%2,%3};"
        : "+f"(c[0]), "+f"(c[1]), "+f"(c[2]), "+f"(c[3])
        : "r"(a0), "r"(a1), "r"(a2), "r"(a3), "r"(b0), "r"(b1));
}
__device__ __forceinline__ void mma_f16(float* c,
    uint32_t a0, uint32_t a1, uint32_t a2, uint32_t a3, uint32_t b0, uint32_t b1) {
    asm volatile(
        "mma.sync.aligned.m16n8k16.row.col.f32.f16.f16.f32 "
        "{%0,%1,%2,%3},{%4,%5,%6,%7},{%8,%9},{%0,%1,%2,%3};"
        : "+f"(c[0]), "+f"(c[1]), "+f"(c[2]), "+f"(c[3])
        : "r"(a0), "r"(a1), "r"(a2), "r"(a3), "r"(b0), "r"(b1));
}
__device__ __forceinline__ uint32_t bf2u(__nv_bfloat162 v) {
    return *reinterpret_cast<uint32_t*>(&v);
}
__device__ __forceinline__ void split2(float a, float b, uint32_t& hi, uint32_t& lo) {
    __nv_bfloat162 h = __floats2bfloat162_rn(a, b);
    __nv_bfloat162 l = __floats2bfloat162_rn(a - __bfloat162float(h.x),
                                             b - __bfloat162float(h.y));
    hi = bf2u(h); lo = bf2u(l);
}
__device__ __forceinline__ uint32_t h2u(__half2 v) {
    return *reinterpret_cast<uint32_t*>(&v);
}
// pack two booleans as fp16x2 {0,1}
__device__ __forceinline__ uint32_t bpack(bool e0, bool e1) {
    return (e0 ? 0x3C00u : 0u) | (e1 ? 0x3C000000u : 0u);
}
#define CPASYNC16(dst, src) \
    asm volatile("cp.async.cg.shared.global [%0], [%1], 16;" :: "r"(dst), "l"(src))
#define CPCOMMIT() asm volatile("cp.async.commit_group;" ::: "memory")
#define CPWAIT(n)  asm volatile("cp.async.wait_group %0;" :: "n"(n) : "memory")

__device__ __forceinline__ uint32_t smem_u32(const void* p) {
    uint32_t a;
    asm("{ .reg .u64 t; cvta.to.shared.u64 t, %1; cvt.u32.u64 %0, t; }"
        : "=r"(a) : "l"(p));
    return a;
}

// ---------------------------------------------------------------------------
// K0: W[512,128] -> W^T hi/lo bf16 [128][512]
// ---------------------------------------------------------------------------
__global__ void k_wprep(const float* __restrict__ W) {
    __shared__ float tile[32][33];
    int k0 = blockIdx.x * 32, n0 = blockIdx.y * 32;
    int tx = threadIdx.x, ty = threadIdx.y;
#pragma unroll
    for (int r = 0; r < 4; r++)
        tile[ty + 8 * r][tx] = W[(size_t)(k0 + ty + 8 * r) * FOUT_ + n0 + tx];
    __syncthreads();
#pragma unroll
    for (int r = 0; r < 4; r++) {
        int n = n0 + ty + 8 * r, k = k0 + tx;
        float x = tile[tx][ty + 8 * r];
        __nv_bfloat16 h = __float2bfloat16_rn(x);
        __nv_bfloat16 l = __float2bfloat16_rn(x - __bfloat162float(h));
        g_WTh[(size_t)n * FIN_ + k] = h;
        g_WTl[(size_t)n * FIN_ + k] = l;
    }
}

// ---------------------------------------------------------------------------
// K1: h = X @ W (bf16 hi/lo 3-MMA, proven). Epilogue: t1/t2, E/F tables,
// and hE/hF fp16 [o][j] (incl. sums row o=128).
// ---------------------------------------------------------------------------
#define GXH 0
#define GXL 17408
#define GWH 34816
#define GWL 69632
#define GA1 104448
#define GA2 104960
#define GE2 105472
#define GF2 105728
#define GSM 105984

__global__ __launch_bounds__(256) void k_gemm_tc(const float* __restrict__ X,
                                                 const float* __restrict__ a1,
                                                 const float* __restrict__ a2) {
    extern __shared__ char sm[];
    const int t = threadIdx.x, w = t >> 5, lane = t & 31;
    const int g = lane >> 2, tig = lane & 3;
    const int wm = w & 3, wn = w >> 2;
    const int row0 = blockIdx.x * 64;

    if (t < 128) {
        ((float*)(sm + GA1))[t] = a1[t];
        ((float*)(sm + GA2))[t] = a2[t];
    }

    float acc[8][4];
#pragma unroll
    for (int nt = 0; nt < 8; nt++)
        acc[nt][0] = acc[nt][1] = acc[nt][2] = acc[nt][3] = 0.f;

    for (int c = 0; c < 8; c++) {
        const int kc = c * 64;
#pragma unroll
        for (int l = 0; l < 4; l++) {
            int f = t + l * 256;
            int m = f >> 4, kq = (f & 15) * 4;
            float4 v = *(const float4*)(X + (size_t)(row0 + m) * FIN_ + kc + kq);
            uint32_t h0, l0, h1, l1;
            split2(v.x, v.y, h0, l0);
            split2(v.z, v.w, h1, l1);
            *(uint2*)(sm + GXH + m * PB + kq * 2) = make_uint2(h0, h1);
            *(uint2*)(sm + GXL + m * PB + kq * 2) = make_uint2(l0, l1);
        }
#pragma unroll
        for (int l = 0; l < 4; l++) {
            int f = t + l * 256;
            int n = f >> 3, kq = (f & 7) * 8;
            *(uint4*)(sm + GWH + n * PB + kq * 2) =
                *(const uint4*)(g_WTh + (size_t)n * FIN_ + kc + kq);
            *(uint4*)(sm + GWL + n * PB + kq * 2) =
                *(const uint4*)(g_WTl + (size_t)n * FIN_ + kc + kq);
        }
        __syncthreads();
#pragma unroll
        for (int ks = 0; ks < 4; ks++) {
            const int kb = (ks * 16 + 2 * tig) * 2;
            const int ra = (wm * 16 + g) * PB, rb = (wm * 16 + g + 8) * PB;
            uint32_t ah0 = *(const uint32_t*)(sm + GXH + ra + kb);
            uint32_t ah1 = *(const uint32_t*)(sm + GXH + rb + kb);
            uint32_t ah2 = *(const uint32_t*)(sm + GXH + ra + kb + 16);
            uint32_t ah3 = *(const uint32_t*)(sm + GXH + rb + kb + 16);
            uint32_t al0 = *(const uint32_t*)(sm + GXL + ra + kb);
            uint32_t al1 = *(const uint32_t*)(sm + GXL + rb + kb);
            uint32_t al2 = *(const uint32_t*)(sm + GXL + ra + kb + 16);
            uint32_t al3 = *(const uint32_t*)(sm + GXL + rb + kb + 16);
#pragma unroll
            for (int nt = 0; nt < 8; nt++) {
                const int n = (wn * 64 + nt * 8 + g) * PB;
                uint32_t bh0 = *(const uint32_t*)(sm + GWH + n + kb);
                uint32_t bh1 = *(const uint32_t*)(sm + GWH + n + kb + 16);
                uint32_t bl0 = *(const uint32_t*)(sm + GWL + n + kb);
                uint32_t bl1 = *(const uint32_t*)(sm + GWL + n + kb + 16);
                mma_bf16(acc[nt], ah0, ah1, ah2, ah3, bh0, bh1);
                mma_bf16(acc[nt], ah0, ah1, ah2, ah3, bl0, bl1);
                mma_bf16(acc[nt], al0, al1, al2, al3, bh0, bh1);
            }
        }
        __syncthreads();
    }

    // ---- epilogue ----
    float* Ds = (float*)sm;   // [64][132] f32, overlays X/W-hi region partly
    {
        const int r = wm * 16 + g, cl = wn * 64 + 2 * tig;
#pragma unroll
        for (int nt = 0; nt < 8; nt++) {
            Ds[r * 132 + cl + nt * 8]           = acc[nt][0];
            Ds[r * 132 + cl + nt * 8 + 1]       = acc[nt][1];
            Ds[(r + 8) * 132 + cl + nt * 8]     = acc[nt][2];
            Ds[(r + 8) * 132 + cl + nt * 8 + 1] = acc[nt][3];
        }
    }
    __syncthreads();
    const float* A1 = (const float*)(sm + GA1);
    const float* A2 = (const float*)(sm + GA2);
    float* E2s = (float*)(sm + GE2);
    float* F2s = (float*)(sm + GF2);
#pragma unroll
    for (int rr = 0; rr < 8; rr++) {
        int r = w * 8 + rr;
        float s1 = 0.f, s2 = 0.f;
#pragma unroll
        for (int q = 0; q < 4; q++) {
            float v = Ds[r * 132 + lane + 32 * q];
            s1 = fmaf(v, A1[lane + 32 * q], s1);
            s2 = fmaf(v, A2[lane + 32 * q], s2);
        }
#pragma unroll
        for (int o = 16; o; o >>= 1) {
            s1 += __shfl_down_sync(0xffffffffu, s1, o);
            s2 += __shfl_down_sync(0xffffffffu, s2, o);
        }
        if (lane == 0) {
            int gr = row0 + r;
            g_t1[gr] = s1;  g_t2[gr] = s2;
            g_E1[gr] = expf(s1);          g_F1[gr] = expf(0.2f * s1);
            E2s[r] = expf(s2);            F2s[r] = expf(0.2f * s2);
        }
    }
    __syncthreads();
    // hE/hF fp16 transposed write: thread -> (o = t&127, half = t>>7)
    {
        const int o = t & 127, half = t >> 7;
        const int bb = row0 >> 11, j0g = row0 & (N_ - 1);
        uint32_t uE[16], uF[16];
#pragma unroll
        for (int ii = 0; ii < 16; ii++) {
            int j0l = half * 32 + 2 * ii;
            float v0 = Ds[j0l * 132 + o], v1 = Ds[(j0l + 1) * 132 + o];
            uE[ii] = h2u(__floats2half2_rn(v0 * E2s[j0l], v1 * E2s[j0l + 1]));
            uF[ii] = h2u(__floats2half2_rn(v0 * F2s[j0l], v1 * F2s[j0l + 1]));
        }
        size_t base = ((size_t)(bb * TROWS) + o) * N_ + j0g + half * 32;
#pragma unroll
        for (int q = 0; q < 4; q++) {
            *(uint4*)(g_hE + base + q * 8) =
                make_uint4(uE[4 * q], uE[4 * q + 1], uE[4 * q + 2], uE[4 * q + 3]);
            *(uint4*)(g_hF + base + q * 8) =
                make_uint4(uF[4 * q], uF[4 * q + 1], uF[4 * q + 2], uF[4 * q + 3]);
        }
        // sums row o=128: E2/F2 values (rows 129..143 stay zero from static init)
        if (t < 64) {
            size_t sbase = ((size_t)(bb * TROWS) + 128) * N_ + j0g + t;
            g_hE[sbase] = __float2half_rn(E2s[t]);
            g_hF[sbase] = __float2half_rn(F2s[t]);
        }
    }
}

// ---------------------------------------------------------------------------
// K2: attention via binary-mask GEMMs:
//   D = diag(E1) * (Mpos @ hE) + diag(F1) * (Mneg @ hF),  sums in col 128.
// CTA = 64 i-rows; 32 chunks of 64 j; cp.async double-buffered B tiles.
// ---------------------------------------------------------------------------
#define AT2  (4 * TILE_B)           // 82944: T2 floats [2048]
#define ADEN (AT2 + 8192)           // 91136: denominators [64]
#define ASM  (ADEN + 256)           // 91392 total

__global__ __launch_bounds__(256) void k_attn_tc(const int* __restrict__ adj,
                                                 const int* __restrict__ d1p,
                                                 const int* __restrict__ d2p,
                                                 float* __restrict__ out) {
    extern __shared__ char sm[];
    const uint32_t smb = smem_u32(sm);
    const int t = threadIdx.x, w = t >> 5, lane = t & 31;
    const int g = lane >> 2, tig = lane & 3;
    const int wm = w & 3, wn = w >> 2;
    const int b = blockIdx.x >> 5, i0 = (blockIdx.x & 31) * 64;
    const int d1 = *d1p, d2 = *d2p;

    float* T2 = (float*)(sm + AT2);
#pragma unroll
    for (int l = 0; l < 2; l++) {
        int f = t + l * 256;
        ((float4*)T2)[f] = ((const float4*)(g_t2 + b * N_))[f];
    }

    const int r0 = i0 + wm * 16 + g, r1 = r0 + 8;
    const int gr0 = b * N_ + r0, gr1 = b * N_ + r1;
    const float nt10 = -g_t1[gr0], E10 = g_E1[gr0], F10 = g_F1[gr0];
    const float nt11 = -g_t1[gr1], E11 = g_E1[gr1], F11 = g_F1[gr1];
    const size_t ab0 = (size_t)gr0 * N_, ab1 = (size_t)gr1 * N_;
    const __half* gEb = g_hE + (size_t)b * TROWS * N_;
    const __half* gFb = g_hF + (size_t)b * TROWS * N_;

    float accE[9][4], accF[9][4];
#pragma unroll
    for (int nt = 0; nt < 9; nt++)
#pragma unroll
        for (int q = 0; q < 4; q++) { accE[nt][q] = 0.f; accF[nt][q] = 0.f; }

    // cp.async chunk loader: 2304 x 16B per chunk (hE 1152 + hF 1152)
    auto load_chunk = [&](int j0, int buf) {
#pragma unroll
        for (int l = 0; l < 9; l++) {
            int f = t + l * 256;
            int mat = f >= 1152;
            int idx = mat ? f - 1152 : f;
            int row = idx >> 3, u = idx & 7;
            const __half* src = (mat ? gFb : gEb) + (size_t)row * N_ + j0 + u * 8;
            uint32_t dst = smb + buf * (2 * TILE_B) + mat * TILE_B + row * PB2 + u * 16;
            CPASYNC16(dst, src);
        }
    };

    load_chunk(0, 0);
    CPCOMMIT();

    const int nbase = wn ? 72 : 0;

    for (int c = 0; c < 32; c++) {
        const int buf = c & 1;
        __syncthreads();                       // buf^1 free to overwrite
        if (c + 1 < 32) {
            load_chunk((c + 1) * 64, buf ^ 1);
            CPCOMMIT();
            CPWAIT(1);
        } else {
            CPWAIT(0);
        }
        __syncthreads();                       // chunk c visible to all

        const uint32_t BE = smb + buf * (2 * TILE_B);
        const uint32_t BF = BE + TILE_B;
        const int j0 = c * 64;
#pragma unroll
        for (int ks = 0; ks < 4; ks++) {
            const int c0 = j0 + ks * 16 + 2 * tig;
            int2 a00 = *(const int2*)(adj + ab0 + c0);
            int2 a01 = *(const int2*)(adj + ab0 + c0 + 8);
            int2 a10 = *(const int2*)(adj + ab1 + c0);
            int2 a11 = *(const int2*)(adj + ab1 + c0 + 8);
            float2 t2a = *(const float2*)(T2 + c0);
            float2 t2b = *(const float2*)(T2 + c0 + 8);

            bool m00 = (a00.x == d1) | (a00.x == d2);
            bool m01 = (a00.y == d1) | (a00.y == d2);
            bool m02 = (a01.x == d1) | (a01.x == d2);
            bool m03 = (a01.y == d1) | (a01.y == d2);
            bool m10 = (a10.x == d1) | (a10.x == d2);
            bool m11 = (a10.y == d1) | (a10.y == d2);
            bool m12 = (a11.x == d1) | (a11.x == d2);
            bool m13 = (a11.y == d1) | (a11.y == d2);
            bool p0a = t2a.x > nt10, p0b = t2a.y > nt10;
            bool p0c = t2b.x > nt10, p0d = t2b.y > nt10;
            bool p1a = t2a.x > nt11, p1b = t2a.y > nt11;
            bool p1c = t2b.x > nt11, p1d = t2b.y > nt11;

            uint32_t aE0 = bpack(m00 && p0a, m01 && p0b);
            uint32_t aE1 = bpack(m10 && p1a, m11 && p1b);
            uint32_t aE2 = bpack(m02 && p0c, m03 && p0d);
            uint32_t aE3 = bpack(m12 && p1c, m13 && p1d);
            uint32_t aF0 = bpack(m00 && !p0a, m01 && !p0b);
            uint32_t aF1 = bpack(m10 && !p1a, m11 && !p1b);
            uint32_t aF2 = bpack(m02 && !p0c, m03 && !p0d);
            uint32_t aF3 = bpack(m12 && !p1c, m13 && !p1d);

            const int kb = (ks * 16 + 2 * tig) * 2;
#pragma unroll
            for (int nt = 0; nt < 9; nt++) {
                const int n = (nbase + nt * 8 + g) * PB2;
                uint32_t bE0 = *(const uint32_t*)(sm + (BE - smb) + n + kb);
                uint32_t bE1 = *(const uint32_t*)(sm + (BE - smb) + n + kb + 16);
                uint32_t bF0 = *(const uint32_t*)(sm + (BF - smb) + n + kb);
                uint32_t bF1 = *(const uint32_t*)(sm + (BF - smb) + n + kb + 16);
                mma_f16(accE[nt], aE0, aE1, aE2, aE3, bE0, bE1);
                mma_f16(accF[nt], aF0, aF1, aF2, aF3, bF0, bF1);
            }
        }
    }

    // denominators: col 128 = wn1, nt=7, tig==0 (elements 0 and 2)
    float* den = (float*)(sm + ADEN);
    if (wn == 1 && tig == 0) {
        den[wm * 16 + g]     = E10 * accE[7][0] + F10 * accF[7][0];
        den[wm * 16 + g + 8] = E11 * accE[7][2] + F11 * accF[7][2];
    }
    __syncthreads();
    const float inv0 = 1.0f / den[wm * 16 + g];
    const float inv1 = 1.0f / den[wm * 16 + g + 8];

#pragma unroll
    for (int nt = 0; nt < 9; nt++) {
        const int n0 = nbase + nt * 8;
        if (n0 >= FOUT_) break;                // wn1: skip sums/zero tiles
        const int cl = n0 + 2 * tig;
        *(float2*)(out + (size_t)gr0 * FOUT_ + cl) =
            make_float2((E10 * accE[nt][0] + F10 * accF[nt][0]) * inv0,
                        (E10 * accE[nt][1] + F10 * accF[nt][1]) * inv0);
        *(float2*)(out + (size_t)gr1 * FOUT_ + cl) =
            make_float2((E11 * accE[nt][2] + F11 * accF[nt][2]) * inv1,
                        (E11 * accE[nt][3] + F11 * accF[nt][3]) * inv1);
    }
}

// ---------------------------------------------------------------------------
extern "C" void kernel_launch(void* const* d_in, const int* in_sizes, int n_in,
                              void* d_out, int out_size) {
    const float* X   = (const float*)d_in[0];
    const float* W   = (const float*)d_in[1];
    const float* a1  = (const float*)d_in[2];
    const float* a2  = (const float*)d_in[3];
    const int*   adj = (const int*)d_in[4];
    // d_in[5] = adj_tree: unused by the reference forward
    const int* d1p = (const int*)d_in[6];
    const int* d2p = (const int*)d_in[7];
    float* out = (float*)d_out;

    k_wprep<<<dim3(FIN_ / 32, FOUT_ / 32), dim3(32, 8)>>>(W);

    cudaFuncSetAttribute(k_gemm_tc, cudaFuncAttributeMaxDynamicSharedMemorySize, GSM);
    k_gemm_tc<<<ROWS_TOT / 64, 256, GSM>>>(X, a1, a2);

    cudaFuncSetAttribute(k_attn_tc, cudaFuncAttributeMaxDynamicSharedMemorySize, ASM);
    k_attn_tc<<<B_ * (N_ / 64), 256, ASM>>>(adj, d1p, d2p, out);
}

// round 6
// speedup vs baseline: 1.9511x; 1.1964x over previous
#include <cuda_runtime.h>
#include <cuda_bf16.h>
#include <cuda_fp16.h>
#include <cstdint>

#define B_    4
#define N_    2048
#define FIN_  512
#define FOUT_ 128
#define ROWS_TOT (B_ * N_)
#define PX    144    // X tile pitch: 64 bf16 = 128B + 16 pad
#define PW    272    // W tile pitch: 128 bf16 = 256B + 16 pad
#define PB2   144    // attn B tile pitch
#define TROWS 136    // o-rows in hE/hF: 128 data + 1 sums + 7 zero pad
#define TILE_B (TROWS * PB2)   // 19584

// ---------------- global scratch (no cudaMalloc allowed) --------------------
__device__ __align__(16) __half g_hE[B_ * TROWS * N_];  // [b][o][j] E2[j]*h; row128=E2; 129+=0
__device__ __align__(16) __half g_hF[B_ * TROWS * N_];  // F2 variant
__device__ float g_t1[ROWS_TOT], g_t2[ROWS_TOT];
__device__ float g_E1[ROWS_TOT], g_F1[ROWS_TOT];

// ---------------- helpers ----------------------------------------------------
__device__ __forceinline__ void mma_bf16(float* c,
    uint32_t a0, uint32_t a1, uint32_t a2, uint32_t a3, uint32_t b0, uint32_t b1) {
    asm volatile(
        "mma.sync.aligned.m16n8k16.row.col.f32.bf16.bf16.f32 "
        "{%0,%1,%2,%3},{%4,%5,%6,%7},{%8,%9},{%0,%1,%2,%3};"
        : "+f"(c[0]), "+f"(c[1]), "+f"(c[2]), "+f"(c[3])
        : "r"(a0), "r"(a1), "r"(a2), "r"(a3), "r"(b0), "r"(b1));
}
__device__ __forceinline__ void mma_f16(float* c,
    uint32_t a0, uint32_t a1, uint32_t a2, uint32_t a3, uint32_t b0, uint32_t b1) {
    asm volatile(
        "mma.sync.aligned.m16n8k16.row.col.f32.f16.f16.f32 "
        "{%0,%1,%2,%3},{%4,%5,%6,%7},{%8,%9},{%0,%1,%2,%3};"
        : "+f"(c[0]), "+f"(c[1]), "+f"(c[2]), "+f"(c[3])
        : "r"(a0), "r"(a1), "r"(a2), "r"(a3), "r"(b0), "r"(b1));
}
#define LDM4(r0, r1, r2, r3, a)                                          \
    asm volatile("ldmatrix.sync.aligned.m8n8.x4.shared.b16 "             \
                 "{%0,%1,%2,%3},[%4];"                                   \
                 : "=r"(r0), "=r"(r1), "=r"(r2), "=r"(r3) : "r"(a))
#define LDM4T(r0, r1, r2, r3, a)                                         \
    asm volatile("ldmatrix.sync.aligned.m8n8.x4.trans.shared.b16 "       \
                 "{%0,%1,%2,%3},[%4];"                                   \
                 : "=r"(r0), "=r"(r1), "=r"(r2), "=r"(r3) : "r"(a))
__device__ __forceinline__ uint32_t bf2u(__nv_bfloat162 v) {
    return *reinterpret_cast<uint32_t*>(&v);
}
__device__ __forceinline__ void split2(float a, float b, uint32_t& hi, uint32_t& lo) {
    __nv_bfloat162 h = __floats2bfloat162_rn(a, b);
    __nv_bfloat162 l = __floats2bfloat162_rn(a - __bfloat162float(h.x),
                                             b - __bfloat162float(h.y));
    hi = bf2u(h); lo = bf2u(l);
}
__device__ __forceinline__ uint32_t h2u(__half2 v) {
    return *reinterpret_cast<uint32_t*>(&v);
}
__device__ __forceinline__ uint32_t bpack(bool e0, bool e1) {
    return (e0 ? 0x3C00u : 0u) | (e1 ? 0x3C000000u : 0u);
}
#define CPASYNC16(dst, src) \
    asm volatile("cp.async.cg.shared.global [%0], [%1], 16;" :: "r"(dst), "l"(src))
#define CPCOMMIT() asm volatile("cp.async.commit_group;" ::: "memory")
#define CPWAIT(n)  asm volatile("cp.async.wait_group %0;" :: "n"(n) : "memory")
__device__ __forceinline__ uint32_t smem_u32(const void* p) {
    uint32_t a;
    asm("{ .reg .u64 t; cvta.to.shared.u64 t, %1; cvt.u32.u64 %0, t; }"
        : "=r"(a) : "l"(p));
    return a;
}

// ---------------------------------------------------------------------------
// K1: h = X @ W (bf16 hi/lo 3-MMA), W split inline from fp32 (no prep kernel).
// X stored [m][k] (ldmatrix), W stored [k][n] (ldmatrix.trans).
// Epilogue: t1/t2, E/F, and hE/hF fp16 [o][j] incl. sums row o=128.
// ---------------------------------------------------------------------------
#define GXH 0
#define GXL 9216
#define GWH 18432
#define GWL 35840
#define GA1 53248
#define GA2 53760
#define GE2 54272
#define GF2 54528
#define GSM 54784

__global__ __launch_bounds__(256) void k_gemm_tc(const float* __restrict__ X,
                                                 const float* __restrict__ W,
                                                 const float* __restrict__ a1,
                                                 const float* __restrict__ a2) {
    extern __shared__ char sm[];
    const uint32_t smb = smem_u32(sm);
    const int t = threadIdx.x, w = t >> 5, lane = t & 31;
    const int wm = w & 3, wn = w >> 2;
    const int row0 = blockIdx.x * 64;

    if (t < 128) {
        ((float*)(sm + GA1))[t] = a1[t];
        ((float*)(sm + GA2))[t] = a2[t];
    }

    float acc[8][4];
#pragma unroll
    for (int nt = 0; nt < 8; nt++)
        acc[nt][0] = acc[nt][1] = acc[nt][2] = acc[nt][3] = 0.f;

    // ldmatrix lane addresses
    const uint32_t ax_off =
        (uint32_t)(wm * 16 + ((lane >> 3) & 1) * 8 + (lane & 7)) * PX +
        (lane >> 4) * 16;
    const uint32_t wl_row = (uint32_t)lane * PW;

    for (int c = 0; c < 8; c++) {
        const int kc = c * 64;
        // X tile: [64 m][64 k] fp32 -> bf16 hi/lo, stored [m][k]
#pragma unroll
        for (int l = 0; l < 4; l++) {
            int f = t + l * 256;
            int m = f >> 4, kq = (f & 15) * 4;
            float4 v = *(const float4*)(X + (size_t)(row0 + m) * FIN_ + kc + kq);
            uint32_t h0, l0, h1, l1;
            split2(v.x, v.y, h0, l0);
            split2(v.z, v.w, h1, l1);
            *(uint2*)(sm + GXH + m * PX + kq * 2) = make_uint2(h0, h1);
            *(uint2*)(sm + GXL + m * PX + kq * 2) = make_uint2(l0, l1);
        }
        // W tile: [64 k][128 n] fp32 -> bf16 hi/lo, stored [k][n]
#pragma unroll
        for (int l = 0; l < 8; l++) {
            int f = t + l * 256;
            int k = f >> 5, nq = (f & 31) * 4;
            float4 v = *(const float4*)(W + (size_t)(kc + k) * FOUT_ + nq);
            uint32_t h0, l0, h1, l1;
            split2(v.x, v.y, h0, l0);
            split2(v.z, v.w, h1, l1);
            *(uint2*)(sm + GWH + k * PW + nq * 2) = make_uint2(h0, h1);
            *(uint2*)(sm + GWL + k * PW + nq * 2) = make_uint2(l0, l1);
        }
        __syncthreads();

        uint32_t ah[4][4], al[4][4];
#pragma unroll
        for (int ks = 0; ks < 4; ks++) {
            LDM4(ah[ks][0], ah[ks][1], ah[ks][2], ah[ks][3],
                 smb + GXH + ax_off + ks * 32);
            LDM4(al[ks][0], al[ks][1], al[ks][2], al[ks][3],
                 smb + GXL + ax_off + ks * 32);
        }
#pragma unroll
        for (int nt = 0; nt < 8; nt++) {
            const int n0 = wn * 64 + nt * 8;
            const uint32_t wadr = smb + GWH + wl_row + n0 * 2;
            uint32_t bh[8], bl[8];
            LDM4T(bh[0], bh[1], bh[2], bh[3], wadr);
            LDM4T(bh[4], bh[5], bh[6], bh[7], wadr + 32 * PW);
            LDM4T(bl[0], bl[1], bl[2], bl[3], wadr + (GWL - GWH));
            LDM4T(bl[4], bl[5], bl[6], bl[7], wadr + (GWL - GWH) + 32 * PW);
#pragma unroll
            for (int ks = 0; ks < 4; ks++) {
                mma_bf16(acc[nt], ah[ks][0], ah[ks][1], ah[ks][2], ah[ks][3],
                         bh[2 * ks], bh[2 * ks + 1]);
                mma_bf16(acc[nt], ah[ks][0], ah[ks][1], ah[ks][2], ah[ks][3],
                         bl[2 * ks], bl[2 * ks + 1]);
                mma_bf16(acc[nt], al[ks][0], al[ks][1], al[ks][2], al[ks][3],
                         bh[2 * ks], bh[2 * ks + 1]);
            }
        }
        __syncthreads();
    }

    // ---- epilogue ----
    const int g = lane >> 2, tig = lane & 3;
    float* Ds = (float*)sm;   // [64][132] f32 = 33792 B (< GA1; tables intact)
    {
        const int r = wm * 16 + g, cl = wn * 64 + 2 * tig;
#pragma unroll
        for (int nt = 0; nt < 8; nt++) {
            Ds[r * 132 + cl + nt * 8]           = acc[nt][0];
            Ds[r * 132 + cl + nt * 8 + 1]       = acc[nt][1];
            Ds[(r + 8) * 132 + cl + nt * 8]     = acc[nt][2];
            Ds[(r + 8) * 132 + cl + nt * 8 + 1] = acc[nt][3];
        }
    }
    __syncthreads();
    const float* A1 = (const float*)(sm + GA1);
    const float* A2 = (const float*)(sm + GA2);
    float* E2s = (float*)(sm + GE2);
    float* F2s = (float*)(sm + GF2);
#pragma unroll
    for (int rr = 0; rr < 8; rr++) {
        int r = w * 8 + rr;
        float s1 = 0.f, s2 = 0.f;
#pragma unroll
        for (int q = 0; q < 4; q++) {
            float v = Ds[r * 132 + lane + 32 * q];
            s1 = fmaf(v, A1[lane + 32 * q], s1);
            s2 = fmaf(v, A2[lane + 32 * q], s2);
        }
#pragma unroll
        for (int o = 16; o; o >>= 1) {
            s1 += __shfl_down_sync(0xffffffffu, s1, o);
            s2 += __shfl_down_sync(0xffffffffu, s2, o);
        }
        if (lane == 0) {
            int gr = row0 + r;
            g_t1[gr] = s1;  g_t2[gr] = s2;
            g_E1[gr] = expf(s1);          g_F1[gr] = expf(0.2f * s1);
            E2s[r] = expf(s2);            F2s[r] = expf(0.2f * s2);
        }
    }
    __syncthreads();
    {
        const int o = t & 127, half = t >> 7;
        const int bb = row0 >> 11, j0g = row0 & (N_ - 1);
        uint32_t uE[16], uF[16];
#pragma unroll
        for (int ii = 0; ii < 16; ii++) {
            int j0l = half * 32 + 2 * ii;
            float v0 = Ds[j0l * 132 + o], v1 = Ds[(j0l + 1) * 132 + o];
            uE[ii] = h2u(__floats2half2_rn(v0 * E2s[j0l], v1 * E2s[j0l + 1]));
            uF[ii] = h2u(__floats2half2_rn(v0 * F2s[j0l], v1 * F2s[j0l + 1]));
        }
        size_t base = ((size_t)(bb * TROWS) + o) * N_ + j0g + half * 32;
#pragma unroll
        for (int q = 0; q < 4; q++) {
            *(uint4*)(g_hE + base + q * 8) =
                make_uint4(uE[4 * q], uE[4 * q + 1], uE[4 * q + 2], uE[4 * q + 3]);
            *(uint4*)(g_hF + base + q * 8) =
                make_uint4(uF[4 * q], uF[4 * q + 1], uF[4 * q + 2], uF[4 * q + 3]);
        }
        if (t < 64) {
            size_t sbase = ((size_t)(bb * TROWS) + 128) * N_ + j0g + t;
            g_hE[sbase] = __float2half_rn(E2s[t]);
            g_hF[sbase] = __float2half_rn(F2s[t]);
        }
    }
}

// ---------------------------------------------------------------------------
// K2: attention via binary-mask GEMMs, ldmatrix B-frags:
//   D = diag(E1)*(Mpos @ hE) + diag(F1)*(Mneg @ hF),  sums in col 128.
// CTA = 64 i-rows; 32 chunks of 64 j; cp.async double-buffered.
// n-tiling: wn0 -> n 0..71 (9 tiles), wn1 -> n 72..135 (8 tiles).
// ---------------------------------------------------------------------------
#define AT2  (4 * TILE_B)           // 78336: T2 floats [2048]
#define ADEN (AT2 + 8192)           // 86528: denominators [64]
#define ASM  (ADEN + 256)           // 86784 total

__global__ __launch_bounds__(256) void k_attn_tc(const int* __restrict__ adj,
                                                 const int* __restrict__ d1p,
                                                 const int* __restrict__ d2p,
                                                 float* __restrict__ out) {
    extern __shared__ char sm[];
    const uint32_t smb = smem_u32(sm);
    const int t = threadIdx.x, w = t >> 5, lane = t & 31;
    const int g = lane >> 2, tig = lane & 3;
    const int wm = w & 3, wn = w >> 2;
    const int b = blockIdx.x >> 5, i0 = (blockIdx.x & 31) * 64;
    const int d1 = *d1p, d2 = *d2p;

    float* T2 = (float*)(sm + AT2);
#pragma unroll
    for (int l = 0; l < 2; l++) {
        int f = t + l * 256;
        ((float4*)T2)[f] = ((const float4*)(g_t2 + b * N_))[f];
    }

    const int r0 = i0 + wm * 16 + g, r1 = r0 + 8;
    const int gr0 = b * N_ + r0, gr1 = b * N_ + r1;
    const float nt10 = -g_t1[gr0], E10 = g_E1[gr0], F10 = g_F1[gr0];
    const float nt11 = -g_t1[gr1], E11 = g_E1[gr1], F11 = g_F1[gr1];
    const size_t ab0 = (size_t)gr0 * N_, ab1 = (size_t)gr1 * N_;
    const __half* gEb = g_hE + (size_t)b * TROWS * N_;
    const __half* gFb = g_hF + (size_t)b * TROWS * N_;

    float accE[9][4], accF[9][4];
#pragma unroll
    for (int nt = 0; nt < 9; nt++)
#pragma unroll
        for (int q = 0; q < 4; q++) { accE[nt][q] = 0.f; accF[nt][q] = 0.f; }

    // cp.async: 136 rows x 8 u16-vectors per matrix = 1088; x2 = 2176 / 256 thr
    auto load_chunk = [&](int j0, int buf) {
#pragma unroll
        for (int l = 0; l < 9; l++) {
            int f = t + l * 256;
            if (f < 2176) {
                int mat = f >= 1088;
                int idx = f - (mat ? 1088 : 0);
                int row = idx >> 3, u = idx & 7;
                const __half* src = (mat ? gFb : gEb) + (size_t)row * N_ + j0 + u * 8;
                uint32_t dst = smb + buf * (2 * TILE_B) + mat * TILE_B + row * PB2 + u * 16;
                CPASYNC16(dst, src);
            }
        }
    };

    load_chunk(0, 0);
    CPCOMMIT();

    const int nbase = wn ? 72 : 0;
    const uint32_t bloff = (uint32_t)(lane & 7) * PB2 + (lane >> 3) * 16;

    for (int c = 0; c < 32; c++) {
        const int buf = c & 1;
        __syncthreads();
        if (c + 1 < 32) {
            load_chunk((c + 1) * 64, buf ^ 1);
            CPCOMMIT();
            CPWAIT(1);
        } else {
            CPWAIT(0);
        }
        __syncthreads();

        const int j0 = c * 64;
        // ---- A-frag build: 4 ks x (aE, aF) ----
        uint32_t aE[4][4], aF[4][4];
#pragma unroll
        for (int ks = 0; ks < 4; ks++) {
            const int c0 = j0 + ks * 16 + 2 * tig;
            int2 a00 = *(const int2*)(adj + ab0 + c0);
            int2 a01 = *(const int2*)(adj + ab0 + c0 + 8);
            int2 a10 = *(const int2*)(adj + ab1 + c0);
            int2 a11 = *(const int2*)(adj + ab1 + c0 + 8);
            float2 t2a = *(const float2*)(T2 + c0);
            float2 t2b = *(const float2*)(T2 + c0 + 8);

            bool m00 = (a00.x == d1) | (a00.x == d2);
            bool m01 = (a00.y == d1) | (a00.y == d2);
            bool m02 = (a01.x == d1) | (a01.x == d2);
            bool m03 = (a01.y == d1) | (a01.y == d2);
            bool m10 = (a10.x == d1) | (a10.x == d2);
            bool m11 = (a10.y == d1) | (a10.y == d2);
            bool m12 = (a11.x == d1) | (a11.x == d2);
            bool m13 = (a11.y == d1) | (a11.y == d2);
            bool p0a = t2a.x > nt10, p0b = t2a.y > nt10;
            bool p0c = t2b.x > nt10, p0d = t2b.y > nt10;
            bool p1a = t2a.x > nt11, p1b = t2a.y > nt11;
            bool p1c = t2b.x > nt11, p1d = t2b.y > nt11;

            aE[ks][0] = bpack(m00 && p0a, m01 && p0b);
            aE[ks][1] = bpack(m10 && p1a, m11 && p1b);
            aE[ks][2] = bpack(m02 && p0c, m03 && p0d);
            aE[ks][3] = bpack(m12 && p1c, m13 && p1d);
            aF[ks][0] = bpack(m00 && !p0a, m01 && !p0b);
            aF[ks][1] = bpack(m10 && !p1a, m11 && !p1b);
            aF[ks][2] = bpack(m02 && !p0c, m03 && !p0d);
            aF[ks][3] = bpack(m12 && !p1c, m13 && !p1d);
        }

        const uint32_t base = smb + buf * (2 * TILE_B);
#define MMA_TILE(NT, N0)                                                      \
        {                                                                     \
            const uint32_t ae = base + (uint32_t)(N0) * PB2 + bloff;          \
            uint32_t bE[8], bF[8];                                            \
            LDM4(bE[0], bE[1], bE[2], bE[3], ae);                             \
            LDM4(bE[4], bE[5], bE[6], bE[7], ae + 64);                        \
            LDM4(bF[0], bF[1], bF[2], bF[3], ae + TILE_B);                    \
            LDM4(bF[4], bF[5], bF[6], bF[7], ae + TILE_B + 64);               \
            _Pragma("unroll")                                                 \
            for (int ks = 0; ks < 4; ks++) {                                  \
                mma_f16(accE[NT], aE[ks][0], aE[ks][1], aE[ks][2], aE[ks][3], \
                        bE[2 * ks], bE[2 * ks + 1]);                          \
                mma_f16(accF[NT], aF[ks][0], aF[ks][1], aF[ks][2], aF[ks][3], \
                        bF[2 * ks], bF[2 * ks + 1]);                          \
            }                                                                 \
        }
#pragma unroll
        for (int nt = 0; nt < 8; nt++) MMA_TILE(nt, nbase + nt * 8);
        if (!wn) MMA_TILE(8, 64);
#undef MMA_TILE
    }

    // denominators: col 128 lives in wn1 tile nt=7 (n0=128), col index 2tig=0
    float* den = (float*)(sm + ADEN);
    if (wn == 1 && tig == 0) {
        den[wm * 16 + g]     = E10 * accE[7][0] + F10 * accF[7][0];
        den[wm * 16 + g + 8] = E11 * accE[7][2] + F11 * accF[7][2];
    }
    __syncthreads();
    const float inv0 = 1.0f / den[wm * 16 + g];
    const float inv1 = 1.0f / den[wm * 16 + g + 8];

#pragma unroll
    for (int nt = 0; nt < 9; nt++) {
        if (wn == 1 && nt >= 7) break;     // nt7 = sums/pad tile
        const int cl = nbase + nt * 8 + 2 * tig;
        *(float2*)(out + (size_t)gr0 * FOUT_ + cl) =
            make_float2((E10 * accE[nt][0] + F10 * accF[nt][0]) * inv0,
                        (E10 * accE[nt][1] + F10 * accF[nt][1]) * inv0);
        *(float2*)(out + (size_t)gr1 * FOUT_ + cl) =
            make_float2((E11 * accE[nt][2] + F11 * accF[nt][2]) * inv1,
                        (E11 * accE[nt][3] + F11 * accF[nt][3]) * inv1);
    }
}

// ---------------------------------------------------------------------------
extern "C" void kernel_launch(void* const* d_in, const int* in_sizes, int n_in,
                              void* d_out, int out_size) {
    const float* X   = (const float*)d_in[0];
    const float* W   = (const float*)d_in[1];
    const float* a1  = (const float*)d_in[2];
    const float* a2  = (const float*)d_in[3];
    const int*   adj = (const int*)d_in[4];
    // d_in[5] = adj_tree: unused by the reference forward
    const int* d1p = (const int*)d_in[6];
    const int* d2p = (const int*)d_in[7];
    float* out = (float*)d_out;

    cudaFuncSetAttribute(k_gemm_tc, cudaFuncAttributeMaxDynamicSharedMemorySize, GSM);
    k_gemm_tc<<<ROWS_TOT / 64, 256, GSM>>>(X, W, a1, a2);

    cudaFuncSetAttribute(k_attn_tc, cudaFuncAttributeMaxDynamicSharedMemorySize, ASM);
    k_attn_tc<<<B_ * (N_ / 64), 256, ASM>>>(adj, d1p, d2p, out);
}